// round 2
// baseline (speedup 1.0000x reference)
#include <cuda_runtime.h>
#include <math.h>

#define B_    64
#define K_    8
#define T_    12
#define H_    2048
#define IN_   2048
#define D_    400
#define E_    128
#define BK_   512
#define G4H_  8192
#define LDIH_ 4224
#define KM1_  7

// ---------------- persistent device scratch (no allocation allowed) ----------------
__device__ float d_Zpre[T_*BK_*G4H_];        // 201 MB: precomputed input-side z per step
__device__ float d_Emb[T_*BK_*E_];
__device__ float d_ZxB[B_*G4H_];
__device__ float d_Z[BK_*G4H_];
__device__ float d_h[BK_*H_];
__device__ float d_c[BK_*H_];
__device__ float d_h2[BK_*H_];
__device__ float d_c2[BK_*H_];
__device__ float d_hd[BK_*H_];
__device__ float d_logits[BK_*D_];
__device__ float d_lpt[BK_*D_];
__device__ float d_gm[BK_*D_];
__device__ float d_G[2][BK_];
__device__ float d_logp[2][BK_];
__device__ float d_samp[2][BK_*T_];
__device__ float d_outs[2][BK_*T_];
__device__ float d_ent[B_];
__device__ float d_wpq[B_*KM1_];
__device__ float d_lgp[B_*KM1_];
__device__ int   d_greedy[BK_];
__device__ int   d_order[BK_];
__device__ int   d_idxk[B_*K_];
__device__ float d_gval[B_*K_];
__device__ float d_entfull[BK_];

__device__ __forceinline__ float sigf(float x) { return 1.f / (1.f + expf(-x)); }

__device__ __forceinline__ unsigned orderf(float f) {
    unsigned u = __float_as_uint(f);
    return (u & 0x80000000u) ? ~u : (u | 0x80000000u);
}
__device__ __forceinline__ float unorderf(unsigned e) {
    unsigned b = (e & 0x80000000u) ? (e ^ 0x80000000u) : ~e;
    return __uint_as_float(b);
}

// ---------------- generic fp32 GEMM: C = act(A @ B^T + Cin + bias) ----------------
// A: [M,K] lda, B: [N,K] ldb (both K-contiguous, "NT"), C/Cin: [M,N] ldc
__global__ __launch_bounds__(256)
void gemm_nt(const float* __restrict__ A, int lda,
             const float* __restrict__ Bm, int ldb,
             const float* __restrict__ Cin, const float* __restrict__ bias,
             float* __restrict__ C, int ldc,
             int M, int N, int K, int do_relu)
{
    __shared__ float As[8][128];
    __shared__ float Bs[8][128];
    int tid = threadIdx.x;
    int bm = blockIdx.y * 128, bn = blockIdx.x * 128;
    int lrow = tid >> 1;
    int lk   = (tid & 1) << 2;
    const float* Ap = A + (size_t)(bm + lrow) * lda + lk;
    const float* Bp = Bm + (size_t)(bn + lrow) * ldb + lk;
    bool aval = (bm + lrow) < M;
    bool bval = (bn + lrow) < N;
    int tx = tid & 15, ty = tid >> 4;
    float acc[8][8];
#pragma unroll
    for (int i = 0; i < 8; i++)
#pragma unroll
        for (int j = 0; j < 8; j++) acc[i][j] = 0.f;

    for (int k0 = 0; k0 < K; k0 += 8) {
        float4 av = make_float4(0.f,0.f,0.f,0.f), bv = make_float4(0.f,0.f,0.f,0.f);
        if (aval) av = *reinterpret_cast<const float4*>(Ap + k0);
        if (bval) bv = *reinterpret_cast<const float4*>(Bp + k0);
        As[lk+0][lrow] = av.x; As[lk+1][lrow] = av.y; As[lk+2][lrow] = av.z; As[lk+3][lrow] = av.w;
        Bs[lk+0][lrow] = bv.x; Bs[lk+1][lrow] = bv.y; Bs[lk+2][lrow] = bv.z; Bs[lk+3][lrow] = bv.w;
        __syncthreads();
#pragma unroll
        for (int kk = 0; kk < 8; kk++) {
            float a[8], b[8];
#pragma unroll
            for (int i = 0; i < 8; i++) a[i] = As[kk][ty*8 + i];
#pragma unroll
            for (int j = 0; j < 8; j++) b[j] = Bs[kk][tx*8 + j];
#pragma unroll
            for (int i = 0; i < 8; i++)
#pragma unroll
                for (int j = 0; j < 8; j++) acc[i][j] = fmaf(a[i], b[j], acc[i][j]);
        }
        __syncthreads();
    }

#pragma unroll
    for (int i = 0; i < 8; i++) {
        int m = bm + ty*8 + i;
        if (m >= M) continue;
#pragma unroll
        for (int j = 0; j < 8; j++) {
            int n = bn + tx*8 + j;
            if (n >= N) continue;
            float v = acc[i][j];
            if (Cin)  v += Cin[(size_t)m*ldc + n];
            if (bias) v += bias[n];
            if (do_relu) v = fmaxf(v, 0.f);
            C[(size_t)m*ldc + n] = v;
        }
    }
}

// ---------------- small kernels ----------------
__global__ void zero_init()
{
    int i = blockIdx.x * blockDim.x + threadIdx.x;
    int stride = gridDim.x * blockDim.x;
    for (int j = i; j < BK_*H_; j += stride) { d_h[j] = 0.f; d_c[j] = 0.f; }
    if (i < BK_)     { d_G[0][i] = 0.f; d_logp[0][i] = 0.f; }
    if (i < BK_*T_)  { d_samp[0][i] = 0.f; d_outs[0][i] = 0.f; }
    if (i < B_)      d_ent[i] = 0.f;
}

__global__ void emb_kernel(const int* __restrict__ pop_all,
                           const float* __restrict__ W_emb,
                           const float* __restrict__ b_emb)
{
    int i = blockIdx.x * blockDim.x + threadIdx.x;
    if (i >= T_*BK_*E_) return;
    int row = i >> 7, e = i & 127;
    int p = pop_all[row];
    float v = W_emb[e*D_ + p] + b_emb[e];
    d_Emb[i] = fmaxf(v, 0.f);
}

__global__ void zpre_init(const float* __restrict__ b_ih, const float* __restrict__ b_hh)
{
    int i = blockIdx.x * blockDim.x + threadIdx.x;
    if (i >= T_*BK_*G4H_) return;
    int j = i & (G4H_ - 1);
    int row = i >> 13;
    int b = row & 63;          // bk % 64 == row % 64  (512 is a multiple of 64)
    d_Zpre[i] = b_ih[j] + b_hh[j] + d_ZxB[b*G4H_ + j];
}

__global__ void lstm_pw()
{
    int i = blockIdx.x * blockDim.x + threadIdx.x;
    if (i >= BK_*H_) return;
    int bk = i >> 11, col = i & 2047;
    const float* zr = d_Z + (size_t)bk * G4H_;
    float zi = zr[col], zf = zr[H_ + col], zg = zr[2*H_ + col], zo = zr[3*H_ + col];
    float cn = sigf(zf) * d_c[i] + sigf(zi) * tanhf(zg);
    d_c2[i] = cn;
    d_h2[i] = sigf(zo) * tanhf(cn);
}

// per-row (bk): masked log_softmax, greedy argmax, and (t>0) the Gumbel-max perturbation g
__global__ void softmax_kernel(const int* __restrict__ pop_t, const float* __restrict__ mask,
                               const float* __restrict__ u_t, int t, int src)
{
    int bk = blockIdx.x, tid = threadIdx.x;   // 128 threads
    __shared__ float sm[D_];
    __shared__ float red[128];
    __shared__ unsigned long long redu[128];
    const float* lrow = d_logits + bk*D_;
    const float* mrow = mask + (size_t)pop_t[bk] * D_;
    float NEG_INF = __int_as_float(0xff800000);

    float lmax = NEG_INF;
    for (int d = tid; d < D_; d += 128) { float v = lrow[d] + mrow[d]; sm[d] = v; lmax = fmaxf(lmax, v); }
    red[tid] = lmax; __syncthreads();
    for (int s = 64; s > 0; s >>= 1) { if (tid < s) red[tid] = fmaxf(red[tid], red[tid+s]); __syncthreads(); }
    float M = red[0]; __syncthreads();

    float ssum = 0.f;
    for (int d = tid; d < D_; d += 128) ssum += expf(sm[d] - M);
    red[tid] = ssum; __syncthreads();
    for (int s = 64; s > 0; s >>= 1) { if (tid < s) red[tid] += red[tid+s]; __syncthreads(); }
    float logZ = M + logf(red[0]);

    // greedy argmax with jax first-index tie-break
    unsigned long long bkey = 0ull;
    for (int d = tid; d < D_; d += 128) {
        unsigned long long key = ((unsigned long long)orderf(sm[d]) << 32) | (unsigned)(0xFFFFFFFFu - d);
        bkey = bkey > key ? bkey : key;
    }
    redu[tid] = bkey; __syncthreads();
    for (int s = 64; s > 0; s >>= 1) { if (tid < s) redu[tid] = redu[tid] > redu[tid+s] ? redu[tid] : redu[tid+s]; __syncthreads(); }
    if (tid == 0) d_greedy[bk] = (int)(0xFFFFFFFFu - (unsigned)(redu[0] & 0xFFFFFFFFu));

    for (int d = tid; d < D_; d += 128) d_lpt[bk*D_ + d] = sm[d] - logZ;

    if (t > 0) {
        float lpc = d_logp[src][bk], Gc = d_G[src][bk];
        __syncthreads();
        for (int d = tid; d < D_; d += 128) {
            float uu = fminf(fmaxf(u_t[bk*D_ + d], 1e-9f), 1.f - 1e-9f);
            float gum = -logf(-logf(uu));
            sm[d] = (sm[d] - logZ) + lpc + gum;    // g_phi
        }
        __syncthreads();
        float m2 = NEG_INF;
        for (int d = tid; d < D_; d += 128) m2 = fmaxf(m2, sm[d]);
        red[tid] = m2; __syncthreads();
        for (int s = 64; s > 0; s >>= 1) { if (tid < s) red[tid] = fmaxf(red[tid], red[tid+s]); __syncthreads(); }
        float Zm = red[0];
        for (int d = tid; d < D_; d += 128) {
            float gp = sm[d];
            float v = Gc - gp + log1pf(-expf(gp - Zm));
            float g = Gc - fmaxf(v, 0.f) - log1pf(expf(-fabsf(v)));
            d_gm[bk*D_ + d] = g;
        }
    }
}

// per image: top-8 of the 3200 candidates g2[b, k*400+d] = g[(k*64+b), d]
// jax top_k semantics: descending by value, smaller index wins ties
__global__ void topk_kernel()
{
    int b = blockIdx.x, tid = threadIdx.x;  // 128 threads
    __shared__ unsigned long long red[128];
    __shared__ unsigned long long picked[K_];
    for (int it = 0; it < K_; it++) {
        unsigned long long best = 0ull;
        for (int cidx = tid; cidx < K_*D_; cidx += 128) {
            int k = cidx / D_, d = cidx - k*D_;
            float v = d_gm[(k*B_ + b)*D_ + d];
            unsigned long long key = ((unsigned long long)orderf(v) << 32) | (unsigned)(0xFFFFFFFFu - cidx);
            bool skip = false;
            for (int j = 0; j < it; j++) if (picked[j] == key) skip = true;
            if (!skip) best = best > key ? best : key;
        }
        red[tid] = best; __syncthreads();
        for (int s = 64; s > 0; s >>= 1) { if (tid < s) red[tid] = red[tid] > red[tid+s] ? red[tid] : red[tid+s]; __syncthreads(); }
        if (tid == 0) {
            unsigned long long w = red[0];
            picked[it] = w;
            d_idxk[b*K_ + it] = (int)(0xFFFFFFFFu - (unsigned)(w & 0xFFFFFFFFu));
            d_gval[b*K_ + it] = unorderf((unsigned)(w >> 32));
        }
        __syncthreads();
    }
}

__global__ void beam_update(int t, int src)
{
    int bk = threadIdx.x;       // 512 threads, 1 block
    int dst = src ^ 1;
    int k = bk >> 6, b = bk & 63;
    int order, sample; float Gn;
    if (t == 0) { order = bk; sample = d_greedy[bk]; Gn = d_G[src][bk]; }
    else {
        int cidx = d_idxk[b*K_ + k];
        int ks = cidx / D_; sample = cidx - ks*D_;
        order = ks*B_ + b;
        Gn = d_gval[b*K_ + k];
    }
    float sel = d_lpt[order*D_ + sample];
    float lp = d_logp[src][order] + ((t == 0) ? 0.f : sel);
    d_G[dst][bk] = Gn; d_logp[dst][bk] = lp; d_order[bk] = order;
    for (int tt = 0; tt < T_; tt++) {
        d_samp[dst][bk*T_ + tt] = d_samp[src][order*T_ + tt];
        d_outs[dst][bk*T_ + tt] = d_outs[src][order*T_ + tt];
    }
    d_samp[dst][bk*T_ + t] = (float)sample;
    d_outs[dst][bk*T_ + t] = sel;
}

__global__ void gather_hc()
{
    int i = blockIdx.x * blockDim.x + threadIdx.x;
    if (i >= BK_*H_) return;
    int bk = i >> 11, col = i & 2047;
    int o = d_order[bk];
    d_h[i] = d_h2[o*H_ + col];
    d_c[i] = d_c2[o*H_ + col];
}

__global__ void entfull_kernel(const int* __restrict__ pop_t, const float* __restrict__ mask)
{
    int warp = threadIdx.x >> 5, lane = threadIdx.x & 31;
    int bk = blockIdx.x * 8 + warp;      // 64 blocks x 8 warps
    int o = d_order[bk];
    const float* lpr = d_lpt + o*D_;
    const float* mrow = mask + (size_t)pop_t[o] * D_;
    float s = 0.f;
    for (int d = lane; d < D_; d += 32) {
        float lp = lpr[d];
        if (mrow[d] == 0.f) s += lp * expf(lp);
    }
    for (int off = 16; off; off >>= 1) s += __shfl_down_sync(0xffffffffu, s, off);
    if (lane == 0) d_entfull[bk] = s;
}

__global__ void wq_kernel(int dst)
{
    int b = threadIdx.x;
    if (b >= B_) return;
    float gk = d_gval[b*K_ + (K_-1)];
    float wsum = 0.f, upd = 0.f;
    for (int k = 0; k < KM1_; k++) {
        float phi = d_logp[dst][k*B_ + b];
        float x = gk - phi;
        float gls;
        if (x >= 10.f) { float y = expf(-x); gls = -x - 0.5f*y + y*y*(1.f/24.f); }
        else gls = logf(-expm1f(-expf(-x)));
        float w = expf(phi - gls);
        d_wpq[b*KM1_ + k] = w;
        d_lgp[b*KM1_ + k] = phi;
        wsum += w;
        upd  += w * d_entfull[k*B_ + b];
    }
    d_ent[b] += upd / wsum;
}

__global__ void epilogue(float* __restrict__ out)
{
    int i = blockIdx.x * blockDim.x + threadIdx.x;
    if (i >= 11712) return;
    if (i < 5376) {
        int b = i / 84, r = i % 84, k = r / T_, tt = r % T_;
        out[i] = d_outs[0][(k*B_ + b)*T_ + tt];
    } else if (i < 10752) {
        int q = i - 5376; int b = q / 84, r = q % 84, k = r / T_, tt = r % T_;
        out[i] = d_samp[0][(k*B_ + b)*T_ + tt];
    } else if (i < 10816) out[i] = d_ent[i - 10752];
    else if (i < 11264)   out[i] = d_wpq[i - 10816];
    else                  out[i] = d_lgp[i - 11264];
}

// ---------------- launch ----------------
extern "C" void kernel_launch(void* const* d_in, const int* in_sizes, int n_in,
                              void* d_out, int out_size)
{
    const float* x_f   = (const float*)d_in[0];
    const float* x_f3  = (const float*)d_in[1];
    const float* gum_u = (const float*)d_in[2];
    const int*   pop   = (const int*)  d_in[3];
    const float* mask  = (const float*)d_in[4];
    const float* W_emb = (const float*)d_in[5];
    const float* b_emb = (const float*)d_in[6];
    const float* W_ih  = (const float*)d_in[7];
    const float* W_hh  = (const float*)d_in[8];
    const float* b_ih  = (const float*)d_in[9];
    const float* b_hh  = (const float*)d_in[10];
    const float* W_fc1 = (const float*)d_in[11];
    const float* b_fc1 = (const float*)d_in[12];
    const float* W_out = (const float*)d_in[13];
    const float* b_out = (const float*)d_in[14];

    float *pZpre, *pEmb, *pZxB, *pZ, *ph, *ph2, *phd, *plogits;
    cudaGetSymbolAddress((void**)&pZpre,   d_Zpre);
    cudaGetSymbolAddress((void**)&pEmb,    d_Emb);
    cudaGetSymbolAddress((void**)&pZxB,    d_ZxB);
    cudaGetSymbolAddress((void**)&pZ,      d_Z);
    cudaGetSymbolAddress((void**)&ph,      d_h);
    cudaGetSymbolAddress((void**)&ph2,     d_h2);
    cudaGetSymbolAddress((void**)&phd,     d_hd);
    cudaGetSymbolAddress((void**)&plogits, d_logits);

    zero_init<<<2048, 512>>>();
    emb_kernel<<<(T_*BK_*E_ + 255)/256, 256>>>(pop, W_emb, b_emb);

    // ZxB = x_f @ W_ih[:, :IN].T       [64, 8192]
    gemm_nt<<<dim3(G4H_/128, 1), 256>>>(x_f, IN_, W_ih, LDIH_, nullptr, nullptr,
                                        pZxB, G4H_, B_, G4H_, IN_, 0);
    // Zpre = bias + ZxB (broadcast over beams and t)
    zpre_init<<<(T_*BK_*G4H_ + 255)/256, 256>>>(b_ih, b_hh);
    // Zpre += Emb @ W_ih[:, IN:IN+E].T     [6144, 8192], K=128
    gemm_nt<<<dim3(G4H_/128, T_*BK_/128), 256>>>(pEmb, E_, W_ih + IN_, LDIH_, pZpre, nullptr,
                                                 pZpre, G4H_, T_*BK_, G4H_, E_, 0);
    // Zpre += x_f3 @ W_ih[:, IN+E:].T      [6144, 8192], K=2048   (dominant GEMM)
    gemm_nt<<<dim3(G4H_/128, T_*BK_/128), 256>>>(x_f3, IN_, W_ih + IN_ + E_, LDIH_, pZpre, nullptr,
                                                 pZpre, G4H_, T_*BK_, G4H_, IN_, 0);

    for (int t = 0; t < T_; t++) {
        int src = t & 1;
        // Z = h @ W_hh.T + Zpre[t]
        gemm_nt<<<dim3(G4H_/128, BK_/128), 256>>>(ph, H_, W_hh, H_,
                                                  pZpre + (size_t)t*BK_*G4H_, nullptr,
                                                  pZ, G4H_, BK_, G4H_, H_, 0);
        lstm_pw<<<(BK_*H_ + 255)/256, 256>>>();
        // hd = relu(h2 @ W_fc1.T + b_fc1)
        gemm_nt<<<dim3(H_/128, BK_/128), 256>>>(ph2, H_, W_fc1, H_, nullptr, b_fc1,
                                                phd, H_, BK_, H_, H_, 1);
        // logits = hd @ W_out.T + b_out
        gemm_nt<<<dim3((D_+127)/128, BK_/128), 256>>>(phd, H_, W_out, H_, nullptr, b_out,
                                                      plogits, D_, BK_, D_, H_, 0);
        softmax_kernel<<<BK_, 128>>>(pop + t*BK_, mask, gum_u + (size_t)t*BK_*D_, t, src);
        if (t > 0) topk_kernel<<<B_, 128>>>();
        beam_update<<<1, BK_>>>(t, src);
        gather_hc<<<(BK_*H_ + 255)/256, 256>>>();
        if (t > 0) {
            entfull_kernel<<<B_, 256>>>(pop + t*BK_, mask);
            wq_kernel<<<1, B_>>>(src ^ 1);
        }
    }
    epilogue<<<(11712 + 255)/256, 256>>>((float*)d_out);
}

// round 3
// speedup vs baseline: 1.4161x; 1.4161x over previous
#include <cuda_runtime.h>
#include <math.h>

#define B_    64
#define K_    8
#define T_    12
#define H_    2048
#define IN_   2048
#define D_    400
#define E_    128
#define BK_   512
#define G4H_  8192
#define LDIH_ 4224
#define KM1_  7

// ---------------- persistent device scratch (no allocation allowed) ----------------
__device__ float d_Zpre[T_*BK_*G4H_];        // 201 MB: precomputed input-side z per step
__device__ float d_Emb[T_*BK_*E_];
__device__ float d_ZxB[B_*G4H_];
__device__ float d_Z[BK_*G4H_];
__device__ float d_h[BK_*H_];
__device__ float d_c[BK_*H_];
__device__ float d_h2[BK_*H_];
__device__ float d_c2[BK_*H_];
__device__ float d_hd[BK_*H_];
__device__ float d_logits[BK_*D_];
__device__ float d_lpt[BK_*D_];
__device__ float d_gm[BK_*D_];
__device__ float d_G[2][BK_];
__device__ float d_logp[2][BK_];
__device__ float d_samp[2][BK_*T_];
__device__ float d_outs[2][BK_*T_];
__device__ float d_ent[B_];
__device__ float d_wpq[B_*KM1_];
__device__ float d_lgp[B_*KM1_];
__device__ int   d_greedy[BK_];
__device__ int   d_order[BK_];
__device__ int   d_idxk[B_*K_];
__device__ float d_gval[B_*K_];
__device__ float d_entfull[BK_];

__device__ __forceinline__ float sigf(float x) { return 1.f / (1.f + expf(-x)); }

__device__ __forceinline__ unsigned orderf(float f) {
    unsigned u = __float_as_uint(f);
    return (u & 0x80000000u) ? ~u : (u | 0x80000000u);
}
__device__ __forceinline__ float unorderf(unsigned e) {
    unsigned b = (e & 0x80000000u) ? (e ^ 0x80000000u) : ~e;
    return __uint_as_float(b);
}

// =====================================================================
// Double-buffered fp32 GEMM:  C = act(A @ B^T [+ Cin] [+ bias] [+ bias2] [+ zxb[m&63]])
// A: [M,K] lda (K-contig), B: [N,K] ldb (K-contig), C/Cin: [M,N] ldc.
// BK = 16, 256 threads, thread tile (BM/16)x(BN/16). K must be a multiple of 16.
// =====================================================================
template<int BM, int BN>
__global__ __launch_bounds__(256, 2)
void gemm_tpl(const float* __restrict__ A, int lda,
              const float* __restrict__ Bm, int ldb,
              const float* __restrict__ Cin,
              const float* __restrict__ bias,
              const float* __restrict__ bias2,
              const float* __restrict__ zxb,
              float* __restrict__ C, int ldc,
              int M, int N, int K, int do_relu)
{
    constexpr int TM = BM / 16;
    constexpr int TN = BN / 16;
    constexpr int LA = BM / 64;     // float4 loads of A per thread per slice
    constexpr int LB = BN / 64;
    constexpr int BMP = BM + 4;
    constexpr int BNP = BN + 4;

    __shared__ float As[2][16][BMP];
    __shared__ float Bs[2][16][BNP];

    const int tid = threadIdx.x;
    const int bm = blockIdx.y * BM;
    const int bn = blockIdx.x * BN;
    const int tx = tid & 15;
    const int ty = tid >> 4;

    float acc[TM][TN];
#pragma unroll
    for (int i = 0; i < TM; i++)
#pragma unroll
        for (int j = 0; j < TN; j++) acc[i][j] = 0.f;

    float4 pa[LA], pb[LB];

    auto fetch = [&](int k0) {
#pragma unroll
        for (int i = 0; i < LA; i++) {
            int lin = tid + 256 * i;
            int r = lin >> 2, kq = (lin & 3) << 2;
            int gr = bm + r;
            pa[i] = (gr < M) ? *reinterpret_cast<const float4*>(A + (size_t)gr * lda + k0 + kq)
                             : make_float4(0.f, 0.f, 0.f, 0.f);
        }
#pragma unroll
        for (int i = 0; i < LB; i++) {
            int lin = tid + 256 * i;
            int r = lin >> 2, kq = (lin & 3) << 2;
            int gr = bn + r;
            pb[i] = (gr < N) ? *reinterpret_cast<const float4*>(Bm + (size_t)gr * ldb + k0 + kq)
                             : make_float4(0.f, 0.f, 0.f, 0.f);
        }
    };

    auto stage = [&](int buf) {
#pragma unroll
        for (int i = 0; i < LA; i++) {
            int lin = tid + 256 * i;
            int r = lin >> 2, kq = (lin & 3) << 2;
            As[buf][kq + 0][r] = pa[i].x;
            As[buf][kq + 1][r] = pa[i].y;
            As[buf][kq + 2][r] = pa[i].z;
            As[buf][kq + 3][r] = pa[i].w;
        }
#pragma unroll
        for (int i = 0; i < LB; i++) {
            int lin = tid + 256 * i;
            int r = lin >> 2, kq = (lin & 3) << 2;
            Bs[buf][kq + 0][r] = pb[i].x;
            Bs[buf][kq + 1][r] = pb[i].y;
            Bs[buf][kq + 2][r] = pb[i].z;
            Bs[buf][kq + 3][r] = pb[i].w;
        }
    };

    auto compute = [&](int buf) {
#pragma unroll
        for (int kk = 0; kk < 16; kk++) {
            float a[TM], b[TN];
#pragma unroll
            for (int i4 = 0; i4 < TM / 4; i4++) {
                float4 v = *reinterpret_cast<const float4*>(&As[buf][kk][ty * TM + i4 * 4]);
                a[i4 * 4 + 0] = v.x; a[i4 * 4 + 1] = v.y; a[i4 * 4 + 2] = v.z; a[i4 * 4 + 3] = v.w;
            }
#pragma unroll
            for (int j4 = 0; j4 < TN / 4; j4++) {
                float4 v = *reinterpret_cast<const float4*>(&Bs[buf][kk][tx * TN + j4 * 4]);
                b[j4 * 4 + 0] = v.x; b[j4 * 4 + 1] = v.y; b[j4 * 4 + 2] = v.z; b[j4 * 4 + 3] = v.w;
            }
#pragma unroll
            for (int i = 0; i < TM; i++)
#pragma unroll
                for (int j = 0; j < TN; j++) acc[i][j] = fmaf(a[i], b[j], acc[i][j]);
        }
    };

    // prologue
    fetch(0);
    stage(0);
    __syncthreads();

    int buf = 0;
    for (int k0 = 16; k0 < K; k0 += 16) {
        fetch(k0);            // LDG for next slice, latency hidden by compute below
        compute(buf);
        stage(buf ^ 1);
        __syncthreads();
        buf ^= 1;
    }
    compute(buf);

    // epilogue
#pragma unroll
    for (int i = 0; i < TM; i++) {
        int m = bm + ty * TM + i;
        if (m >= M) continue;
#pragma unroll
        for (int j = 0; j < TN; j++) {
            int n = bn + tx * TN + j;
            if (n >= N) continue;
            float v = acc[i][j];
            if (Cin)   v += Cin[(size_t)m * ldc + n];
            if (bias)  v += bias[n];
            if (bias2) v += bias2[n];
            if (zxb)   v += zxb[(size_t)(m & 63) * ldc + n];
            if (do_relu) v = fmaxf(v, 0.f);
            C[(size_t)m * ldc + n] = v;
        }
    }
}

// ---------------- small kernels ----------------
__global__ void zero_init()
{
    int i = blockIdx.x * blockDim.x + threadIdx.x;
    int stride = gridDim.x * blockDim.x;
    for (int j = i; j < BK_*H_; j += stride) { d_h[j] = 0.f; d_c[j] = 0.f; }
    if (i < BK_)     { d_G[0][i] = 0.f; d_logp[0][i] = 0.f; }
    if (i < BK_*T_)  { d_samp[0][i] = 0.f; d_outs[0][i] = 0.f; }
    if (i < B_)      d_ent[i] = 0.f;
}

__global__ void emb_kernel(const int* __restrict__ pop_all,
                           const float* __restrict__ W_emb,
                           const float* __restrict__ b_emb)
{
    int i = blockIdx.x * blockDim.x + threadIdx.x;
    if (i >= T_*BK_*E_) return;
    int row = i >> 7, e = i & 127;
    int p = pop_all[row];
    float v = W_emb[e*D_ + p] + b_emb[e];
    d_Emb[i] = fmaxf(v, 0.f);
}

__global__ void lstm_pw()
{
    int i = blockIdx.x * blockDim.x + threadIdx.x;
    if (i >= BK_*H_) return;
    int bk = i >> 11, col = i & 2047;
    const float* zr = d_Z + (size_t)bk * G4H_;
    float zi = zr[col], zf = zr[H_ + col], zg = zr[2*H_ + col], zo = zr[3*H_ + col];
    float cn = sigf(zf) * d_c[i] + sigf(zi) * tanhf(zg);
    d_c2[i] = cn;
    d_h2[i] = sigf(zo) * tanhf(cn);
}

// per-row (bk): masked log_softmax, greedy argmax, and (t>0) the Gumbel-max perturbation g
__global__ void softmax_kernel(const int* __restrict__ pop_t, const float* __restrict__ mask,
                               const float* __restrict__ u_t, int t, int src)
{
    int bk = blockIdx.x, tid = threadIdx.x;   // 128 threads
    __shared__ float sm[D_];
    __shared__ float red[128];
    __shared__ unsigned long long redu[128];
    const float* lrow = d_logits + bk*D_;
    const float* mrow = mask + (size_t)pop_t[bk] * D_;
    float NEG_INF = __int_as_float(0xff800000);

    float lmax = NEG_INF;
    for (int d = tid; d < D_; d += 128) { float v = lrow[d] + mrow[d]; sm[d] = v; lmax = fmaxf(lmax, v); }
    red[tid] = lmax; __syncthreads();
    for (int s = 64; s > 0; s >>= 1) { if (tid < s) red[tid] = fmaxf(red[tid], red[tid+s]); __syncthreads(); }
    float M = red[0]; __syncthreads();

    float ssum = 0.f;
    for (int d = tid; d < D_; d += 128) ssum += expf(sm[d] - M);
    red[tid] = ssum; __syncthreads();
    for (int s = 64; s > 0; s >>= 1) { if (tid < s) red[tid] += red[tid+s]; __syncthreads(); }
    float logZ = M + logf(red[0]);

    // greedy argmax with jax first-index tie-break
    unsigned long long bkey = 0ull;
    for (int d = tid; d < D_; d += 128) {
        unsigned long long key = ((unsigned long long)orderf(sm[d]) << 32) | (unsigned)(0xFFFFFFFFu - d);
        bkey = bkey > key ? bkey : key;
    }
    redu[tid] = bkey; __syncthreads();
    for (int s = 64; s > 0; s >>= 1) { if (tid < s) redu[tid] = redu[tid] > redu[tid+s] ? redu[tid] : redu[tid+s]; __syncthreads(); }
    if (tid == 0) d_greedy[bk] = (int)(0xFFFFFFFFu - (unsigned)(redu[0] & 0xFFFFFFFFu));

    for (int d = tid; d < D_; d += 128) d_lpt[bk*D_ + d] = sm[d] - logZ;

    if (t > 0) {
        float lpc = d_logp[src][bk], Gc = d_G[src][bk];
        __syncthreads();
        for (int d = tid; d < D_; d += 128) {
            float uu = fminf(fmaxf(u_t[bk*D_ + d], 1e-9f), 1.f - 1e-9f);
            float gum = -logf(-logf(uu));
            sm[d] = (sm[d] - logZ) + lpc + gum;    // g_phi
        }
        __syncthreads();
        float m2 = NEG_INF;
        for (int d = tid; d < D_; d += 128) m2 = fmaxf(m2, sm[d]);
        red[tid] = m2; __syncthreads();
        for (int s = 64; s > 0; s >>= 1) { if (tid < s) red[tid] = fmaxf(red[tid], red[tid+s]); __syncthreads(); }
        float Zm = red[0];
        for (int d = tid; d < D_; d += 128) {
            float gp = sm[d];
            float v = Gc - gp + log1pf(-expf(gp - Zm));
            float g = Gc - fmaxf(v, 0.f) - log1pf(expf(-fabsf(v)));
            d_gm[bk*D_ + d] = g;
        }
    }
}

// per image: top-8 of the 3200 candidates g2[b, k*400+d] = g[(k*64+b), d]
__global__ void topk_kernel()
{
    int b = blockIdx.x, tid = threadIdx.x;  // 128 threads
    __shared__ unsigned long long red[128];
    __shared__ unsigned long long picked[K_];
    for (int it = 0; it < K_; it++) {
        unsigned long long best = 0ull;
        for (int cidx = tid; cidx < K_*D_; cidx += 128) {
            int k = cidx / D_, d = cidx - k*D_;
            float v = d_gm[(k*B_ + b)*D_ + d];
            unsigned long long key = ((unsigned long long)orderf(v) << 32) | (unsigned)(0xFFFFFFFFu - cidx);
            bool skip = false;
            for (int j = 0; j < it; j++) if (picked[j] == key) skip = true;
            if (!skip) best = best > key ? best : key;
        }
        red[tid] = best; __syncthreads();
        for (int s = 64; s > 0; s >>= 1) { if (tid < s) red[tid] = red[tid] > red[tid+s] ? red[tid] : red[tid+s]; __syncthreads(); }
        if (tid == 0) {
            unsigned long long w = red[0];
            picked[it] = w;
            d_idxk[b*K_ + it] = (int)(0xFFFFFFFFu - (unsigned)(w & 0xFFFFFFFFu));
            d_gval[b*K_ + it] = unorderf((unsigned)(w >> 32));
        }
        __syncthreads();
    }
}

__global__ void beam_update(int t, int src)
{
    int bk = threadIdx.x;       // 512 threads, 1 block
    int dst = src ^ 1;
    int k = bk >> 6, b = bk & 63;
    int order, sample; float Gn;
    if (t == 0) { order = bk; sample = d_greedy[bk]; Gn = d_G[src][bk]; }
    else {
        int cidx = d_idxk[b*K_ + k];
        int ks = cidx / D_; sample = cidx - ks*D_;
        order = ks*B_ + b;
        Gn = d_gval[b*K_ + k];
    }
    float sel = d_lpt[order*D_ + sample];
    float lp = d_logp[src][order] + ((t == 0) ? 0.f : sel);
    d_G[dst][bk] = Gn; d_logp[dst][bk] = lp; d_order[bk] = order;
    for (int tt = 0; tt < T_; tt++) {
        d_samp[dst][bk*T_ + tt] = d_samp[src][order*T_ + tt];
        d_outs[dst][bk*T_ + tt] = d_outs[src][order*T_ + tt];
    }
    d_samp[dst][bk*T_ + t] = (float)sample;
    d_outs[dst][bk*T_ + t] = sel;
}

__global__ void gather_hc()
{
    int i = blockIdx.x * blockDim.x + threadIdx.x;
    if (i >= BK_*H_) return;
    int bk = i >> 11, col = i & 2047;
    int o = d_order[bk];
    d_h[i] = d_h2[o*H_ + col];
    d_c[i] = d_c2[o*H_ + col];
}

__global__ void entfull_kernel(const int* __restrict__ pop_t, const float* __restrict__ mask)
{
    int warp = threadIdx.x >> 5, lane = threadIdx.x & 31;
    int bk = blockIdx.x * 8 + warp;      // 64 blocks x 8 warps
    int o = d_order[bk];
    const float* lpr = d_lpt + o*D_;
    const float* mrow = mask + (size_t)pop_t[o] * D_;
    float s = 0.f;
    for (int d = lane; d < D_; d += 32) {
        float lp = lpr[d];
        if (mrow[d] == 0.f) s += lp * expf(lp);
    }
    for (int off = 16; off; off >>= 1) s += __shfl_down_sync(0xffffffffu, s, off);
    if (lane == 0) d_entfull[bk] = s;
}

__global__ void wq_kernel(int dst)
{
    int b = threadIdx.x;
    if (b >= B_) return;
    float gk = d_gval[b*K_ + (K_-1)];
    float wsum = 0.f, upd = 0.f;
    for (int k = 0; k < KM1_; k++) {
        float phi = d_logp[dst][k*B_ + b];
        float x = gk - phi;
        float gls;
        if (x >= 10.f) { float y = expf(-x); gls = -x - 0.5f*y + y*y*(1.f/24.f); }
        else gls = logf(-expm1f(-expf(-x)));
        float w = expf(phi - gls);
        d_wpq[b*KM1_ + k] = w;
        d_lgp[b*KM1_ + k] = phi;
        wsum += w;
        upd  += w * d_entfull[k*B_ + b];
    }
    d_ent[b] += upd / wsum;
}

__global__ void epilogue(float* __restrict__ out)
{
    int i = blockIdx.x * blockDim.x + threadIdx.x;
    if (i >= 11712) return;
    if (i < 5376) {
        int b = i / 84, r = i % 84, k = r / T_, tt = r % T_;
        out[i] = d_outs[0][(k*B_ + b)*T_ + tt];
    } else if (i < 10752) {
        int q = i - 5376; int b = q / 84, r = q % 84, k = r / T_, tt = r % T_;
        out[i] = d_samp[0][(k*B_ + b)*T_ + tt];
    } else if (i < 10816) out[i] = d_ent[i - 10752];
    else if (i < 11264)   out[i] = d_wpq[i - 10816];
    else                  out[i] = d_lgp[i - 11264];
}

// ---------------- launch ----------------
extern "C" void kernel_launch(void* const* d_in, const int* in_sizes, int n_in,
                              void* d_out, int out_size)
{
    const float* x_f   = (const float*)d_in[0];
    const float* x_f3  = (const float*)d_in[1];
    const float* gum_u = (const float*)d_in[2];
    const int*   pop   = (const int*)  d_in[3];
    const float* mask  = (const float*)d_in[4];
    const float* W_emb = (const float*)d_in[5];
    const float* b_emb = (const float*)d_in[6];
    const float* W_ih  = (const float*)d_in[7];
    const float* W_hh  = (const float*)d_in[8];
    const float* b_ih  = (const float*)d_in[9];
    const float* b_hh  = (const float*)d_in[10];
    const float* W_fc1 = (const float*)d_in[11];
    const float* b_fc1 = (const float*)d_in[12];
    const float* W_out = (const float*)d_in[13];
    const float* b_out = (const float*)d_in[14];

    float *pZpre, *pEmb, *pZxB, *pZ, *ph, *ph2, *phd, *plogits;
    cudaGetSymbolAddress((void**)&pZpre,   d_Zpre);
    cudaGetSymbolAddress((void**)&pEmb,    d_Emb);
    cudaGetSymbolAddress((void**)&pZxB,    d_ZxB);
    cudaGetSymbolAddress((void**)&pZ,      d_Z);
    cudaGetSymbolAddress((void**)&ph,      d_h);
    cudaGetSymbolAddress((void**)&ph2,     d_h2);
    cudaGetSymbolAddress((void**)&phd,     d_hd);
    cudaGetSymbolAddress((void**)&plogits, d_logits);

    zero_init<<<2048, 512>>>();
    emb_kernel<<<(T_*BK_*E_ + 255)/256, 256>>>(pop, W_emb, b_emb);

    // ZxB = x_f @ W_ih[:, :IN].T       [64, 8192]
    gemm_tpl<64,128><<<dim3(G4H_/128, 1), 256>>>(
        x_f, IN_, W_ih, LDIH_, nullptr, nullptr, nullptr, nullptr,
        pZxB, G4H_, B_, G4H_, IN_, 0);

    // Zpre = Emb @ W_ih[:, IN:IN+E].T + (b_ih + b_hh + ZxB[b])   [6144, 8192], K=128
    gemm_tpl<128,128><<<dim3(G4H_/128, T_*BK_/128), 256>>>(
        pEmb, E_, W_ih + IN_, LDIH_, nullptr, b_ih, b_hh, pZxB,
        pZpre, G4H_, T_*BK_, G4H_, E_, 0);

    // Zpre += x_f3 @ W_ih[:, IN+E:].T      [6144, 8192], K=2048   (dominant GEMM)
    gemm_tpl<128,128><<<dim3(G4H_/128, T_*BK_/128), 256>>>(
        x_f3, IN_, W_ih + IN_ + E_, LDIH_, pZpre, nullptr, nullptr, nullptr,
        pZpre, G4H_, T_*BK_, G4H_, IN_, 0);

    for (int t = 0; t < T_; t++) {
        int src = t & 1;
        // Z = h @ W_hh.T + Zpre[t]
        gemm_tpl<128,128><<<dim3(G4H_/128, BK_/128), 256>>>(
            ph, H_, W_hh, H_, pZpre + (size_t)t*BK_*G4H_, nullptr, nullptr, nullptr,
            pZ, G4H_, BK_, G4H_, H_, 0);
        lstm_pw<<<(BK_*H_ + 255)/256, 256>>>();
        // hd = relu(h2 @ W_fc1.T + b_fc1)   [512, 2048]  -> 64x128 tiles, 128 CTAs
        gemm_tpl<64,128><<<dim3(H_/128, BK_/64), 256>>>(
            ph2, H_, W_fc1, H_, nullptr, b_fc1, nullptr, nullptr,
            phd, H_, BK_, H_, H_, 1);
        // logits = hd @ W_out.T + b_out     [512, 400]
        gemm_tpl<64,128><<<dim3((D_+127)/128, BK_/64), 256>>>(
            phd, H_, W_out, H_, nullptr, b_out, nullptr, nullptr,
            plogits, D_, BK_, D_, H_, 0);
        softmax_kernel<<<BK_, 128>>>(pop + t*BK_, mask, gum_u + (size_t)t*BK_*D_, t, src);
        if (t > 0) topk_kernel<<<B_, 128>>>();
        beam_update<<<1, BK_>>>(t, src);
        gather_hc<<<(BK_*H_ + 255)/256, 256>>>();
        if (t > 0) {
            entfull_kernel<<<B_, 256>>>(pop + t*BK_, mask);
            wq_kernel<<<1, B_>>>(src ^ 1);
        }
    }
    epilogue<<<(11712 + 255)/256, 256>>>((float*)d_out);
}

// round 4
// speedup vs baseline: 1.9219x; 1.3571x over previous
#include <cuda_runtime.h>
#include <math.h>

#define B_    64
#define K_    8
#define T_    12
#define H_    2048
#define IN_   2048
#define D_    400
#define E_    128
#define BK_   512
#define G4H_  8192
#define LDIH_ 4224
#define KM1_  7

// ---------------- persistent device scratch (no allocation allowed) ----------------
__device__ float d_Zpre[T_*BK_*G4H_];        // 201 MB: precomputed input-side z per step
__device__ float d_Emb[T_*BK_*E_];
__device__ float d_ZxB[B_*G4H_];
__device__ float d_zxbpart[4*B_*G4H_];
__device__ float d_logpart[4*BK_*D_];
__device__ float d_Z[BK_*G4H_];
__device__ float d_h[BK_*H_];
__device__ float d_c[BK_*H_];
__device__ float d_h2[BK_*H_];
__device__ float d_c2[BK_*H_];
__device__ float d_hd[BK_*H_];
__device__ float d_logits[BK_*D_];
__device__ float d_lpt[BK_*D_];
__device__ float d_gm[BK_*D_];
__device__ float d_G[2][BK_];
__device__ float d_logp[2][BK_];
__device__ float d_samp[2][BK_*T_];
__device__ float d_outs[2][BK_*T_];
__device__ float d_ent[B_];
__device__ float d_wpq[B_*KM1_];
__device__ float d_lgp[B_*KM1_];
__device__ int   d_greedy[BK_];
__device__ int   d_order[BK_];
__device__ int   d_idxk[B_*K_];
__device__ float d_gval[B_*K_];
__device__ float d_entfull[BK_];

__device__ __forceinline__ float sigf(float x) { return 1.f / (1.f + expf(-x)); }

__device__ __forceinline__ unsigned orderf(float f) {
    unsigned u = __float_as_uint(f);
    return (u & 0x80000000u) ? ~u : (u | 0x80000000u);
}
__device__ __forceinline__ float unorderf(unsigned e) {
    unsigned b = (e & 0x80000000u) ? (e ^ 0x80000000u) : ~e;
    return __uint_as_float(b);
}

__device__ __forceinline__ unsigned long long pk2(float lo, float hi) {
    unsigned long long r;
    asm("mov.b64 %0, {%1, %2};" : "=l"(r) : "f"(lo), "f"(hi));
    return r;
}
__device__ __forceinline__ void upk2(unsigned long long v, float& lo, float& hi) {
    asm("mov.b64 {%0, %1}, %2;" : "=f"(lo), "=f"(hi) : "l"(v));
}

// =====================================================================
// Double-buffered fp32 GEMM with packed FFMA2 (fma.rn.f32x2):
//   C = act(A @ B^T [+ Cin] [+ bias] [+ bias2] [+ zxb[m&63]])
// A: [M,K] lda (K-contig), B: [N,K] ldb (K-contig), C/Cin: [M,N] ldc.
// BK = 16, 256 threads, thread tile (BM/16)x8, acc packed in pairs along M.
// If kchunk != 0: split-K along gridDim.z; partial outputs stacked in C.
// =====================================================================
template<int BM, int BN>
__global__ __launch_bounds__(256, 2)
void gemm_tpl(const float* __restrict__ A, int lda,
              const float* __restrict__ Bm, int ldb,
              const float* __restrict__ Cin,
              const float* __restrict__ bias,
              const float* __restrict__ bias2,
              const float* __restrict__ zxb,
              float* __restrict__ C, int ldc,
              int M, int N, int K, int do_relu, int kchunk)
{
    static_assert(BN == 128, "BN must be 128");
    constexpr int TM = BM / 16;          // 8 or 4
    constexpr int TN = 8;
    constexpr int LA = BM / 64;
    constexpr int LB = BN / 64;
    constexpr int BMP = BM + 4;
    constexpr int BNP = BN + 4;

    if (kchunk) {
        int kz = blockIdx.z;
        A  += (size_t)kz * kchunk;
        Bm += (size_t)kz * kchunk;
        C  += (size_t)kz * M * ldc;
        K = kchunk;
    }

    __shared__ float As[2][16][BMP];
    __shared__ float Bs[2][16][BNP];

    const int tid = threadIdx.x;
    const int bm = blockIdx.y * BM;
    const int bn = blockIdx.x * BN;
    const int tx = tid & 15;
    const int ty = tid >> 4;

    unsigned long long acc2[TM/2][TN];
#pragma unroll
    for (int i = 0; i < TM/2; i++)
#pragma unroll
        for (int j = 0; j < TN; j++) acc2[i][j] = 0ull;

    float4 pa[LA], pb[LB];

    auto fetch = [&](int k0) {
#pragma unroll
        for (int i = 0; i < LA; i++) {
            int lin = tid + 256 * i;
            int r = lin >> 2, kq = (lin & 3) << 2;
            int gr = bm + r;
            pa[i] = (gr < M) ? *reinterpret_cast<const float4*>(A + (size_t)gr * lda + k0 + kq)
                             : make_float4(0.f, 0.f, 0.f, 0.f);
        }
#pragma unroll
        for (int i = 0; i < LB; i++) {
            int lin = tid + 256 * i;
            int r = lin >> 2, kq = (lin & 3) << 2;
            int gr = bn + r;
            pb[i] = (gr < N) ? *reinterpret_cast<const float4*>(Bm + (size_t)gr * ldb + k0 + kq)
                             : make_float4(0.f, 0.f, 0.f, 0.f);
        }
    };

    auto stage = [&](int buf) {
#pragma unroll
        for (int i = 0; i < LA; i++) {
            int lin = tid + 256 * i;
            int r = lin >> 2, kq = (lin & 3) << 2;
            As[buf][kq + 0][r] = pa[i].x;
            As[buf][kq + 1][r] = pa[i].y;
            As[buf][kq + 2][r] = pa[i].z;
            As[buf][kq + 3][r] = pa[i].w;
        }
#pragma unroll
        for (int i = 0; i < LB; i++) {
            int lin = tid + 256 * i;
            int r = lin >> 2, kq = (lin & 3) << 2;
            Bs[buf][kq + 0][r] = pb[i].x;
            Bs[buf][kq + 1][r] = pb[i].y;
            Bs[buf][kq + 2][r] = pb[i].z;
            Bs[buf][kq + 3][r] = pb[i].w;
        }
    };

    auto compute = [&](int buf) {
#pragma unroll
        for (int kk = 0; kk < 16; kk++) {
            // A pairs straight from smem (broadcast across the 16 lanes of a ty-group)
            unsigned long long ap[TM/2];
#pragma unroll
            for (int i2 = 0; i2 < TM/2; i2++) {
                int off;
                if (TM == 8) off = (i2 < 2) ? (ty*4 + 2*i2) : (64 + ty*4 + 2*(i2-2));
                else         off = ty*4 + 2*i2;
                ap[i2] = *reinterpret_cast<const unsigned long long*>(&As[buf][kk][off]);
            }
            // B fragment: two conflict-free contiguous float4 reads, then splat
            float b[TN];
            {
                float4 v = *reinterpret_cast<const float4*>(&Bs[buf][kk][tx*4]);
                b[0]=v.x; b[1]=v.y; b[2]=v.z; b[3]=v.w;
                float4 w = *reinterpret_cast<const float4*>(&Bs[buf][kk][64 + tx*4]);
                b[4]=w.x; b[5]=w.y; b[6]=w.z; b[7]=w.w;
            }
            unsigned long long bs[TN];
#pragma unroll
            for (int j = 0; j < TN; j++) bs[j] = pk2(b[j], b[j]);
#pragma unroll
            for (int i2 = 0; i2 < TM/2; i2++)
#pragma unroll
                for (int j = 0; j < TN; j++)
                    asm("fma.rn.f32x2 %0, %1, %2, %0;"
                        : "+l"(acc2[i2][j]) : "l"(ap[i2]), "l"(bs[j]));
        }
    };

    fetch(0);
    stage(0);
    __syncthreads();

    int buf = 0;
    for (int k0 = 16; k0 < K; k0 += 16) {
        fetch(k0);
        compute(buf);
        stage(buf ^ 1);
        __syncthreads();
        buf ^= 1;
    }
    compute(buf);

    // epilogue
#pragma unroll
    for (int i2 = 0; i2 < TM/2; i2++) {
        int mo;
        if (TM == 8) mo = (i2 < 2) ? (ty*4 + 2*i2) : (64 + ty*4 + 2*(i2-2));
        else         mo = ty*4 + 2*i2;
#pragma unroll
        for (int j = 0; j < TN; j++) {
            int n = bn + ((j < 4) ? (tx*4 + j) : (64 + tx*4 + (j-4)));
            if (n >= N) continue;
            float lo, hi;
            upk2(acc2[i2][j], lo, hi);
#pragma unroll
            for (int r = 0; r < 2; r++) {
                int m = bm + mo + r;
                if (m >= M) continue;
                float v = (r == 0) ? lo : hi;
                if (Cin)   v += Cin[(size_t)m * ldc + n];
                if (bias)  v += bias[n];
                if (bias2) v += bias2[n];
                if (zxb)   v += zxb[(size_t)(m & 63) * ldc + n];
                if (do_relu) v = fmaxf(v, 0.f);
                C[(size_t)m * ldc + n] = v;
            }
        }
    }
}

// deterministic split-K reduction: out[i] = sum_p parts[p*total+i] (+ bias[i%ncols])
__global__ void reduce_k(const float* __restrict__ parts, int nparts, int total,
                         int ncols, const float* __restrict__ bias,
                         float* __restrict__ out)
{
    int i = blockIdx.x * blockDim.x + threadIdx.x;
    if (i >= total) return;
    float s = 0.f;
    for (int p = 0; p < nparts; p++) s += parts[(size_t)p * total + i];
    if (bias) s += bias[i % ncols];
    out[i] = s;
}

// ---------------- small kernels ----------------
__global__ void zero_init()
{
    int i = blockIdx.x * blockDim.x + threadIdx.x;
    int stride = gridDim.x * blockDim.x;
    for (int j = i; j < BK_*H_; j += stride) { d_h[j] = 0.f; d_c[j] = 0.f; }
    if (i < BK_)     { d_G[0][i] = 0.f; d_logp[0][i] = 0.f; }
    if (i < BK_*T_)  { d_samp[0][i] = 0.f; d_outs[0][i] = 0.f; }
    if (i < B_)      d_ent[i] = 0.f;
}

__global__ void emb_kernel(const int* __restrict__ pop_all,
                           const float* __restrict__ W_emb,
                           const float* __restrict__ b_emb)
{
    int i = blockIdx.x * blockDim.x + threadIdx.x;
    if (i >= T_*BK_*E_) return;
    int row = i >> 7, e = i & 127;
    int p = pop_all[row];
    float v = W_emb[e*D_ + p] + b_emb[e];
    d_Emb[i] = fmaxf(v, 0.f);
}

__global__ void lstm_pw()
{
    int i = blockIdx.x * blockDim.x + threadIdx.x;
    if (i >= BK_*H_) return;
    int bk = i >> 11, col = i & 2047;
    const float* zr = d_Z + (size_t)bk * G4H_;
    float zi = zr[col], zf = zr[H_ + col], zg = zr[2*H_ + col], zo = zr[3*H_ + col];
    float cn = sigf(zf) * d_c[i] + sigf(zi) * tanhf(zg);
    d_c2[i] = cn;
    d_h2[i] = sigf(zo) * tanhf(cn);
}

// per-row (bk): masked log_softmax, greedy argmax, and (t>0) the Gumbel-max perturbation g
__global__ void softmax_kernel(const int* __restrict__ pop_t, const float* __restrict__ mask,
                               const float* __restrict__ u_t, int t, int src)
{
    int bk = blockIdx.x, tid = threadIdx.x;   // 128 threads
    __shared__ float sm[D_];
    __shared__ float red[128];
    __shared__ unsigned long long redu[128];
    const float* lrow = d_logits + bk*D_;
    const float* mrow = mask + (size_t)pop_t[bk] * D_;
    float NEG_INF = __int_as_float(0xff800000);

    float lmax = NEG_INF;
    for (int d = tid; d < D_; d += 128) { float v = lrow[d] + mrow[d]; sm[d] = v; lmax = fmaxf(lmax, v); }
    red[tid] = lmax; __syncthreads();
    for (int s = 64; s > 0; s >>= 1) { if (tid < s) red[tid] = fmaxf(red[tid], red[tid+s]); __syncthreads(); }
    float M = red[0]; __syncthreads();

    float ssum = 0.f;
    for (int d = tid; d < D_; d += 128) ssum += expf(sm[d] - M);
    red[tid] = ssum; __syncthreads();
    for (int s = 64; s > 0; s >>= 1) { if (tid < s) red[tid] += red[tid+s]; __syncthreads(); }
    float logZ = M + logf(red[0]);

    // greedy argmax with jax first-index tie-break
    unsigned long long bkey = 0ull;
    for (int d = tid; d < D_; d += 128) {
        unsigned long long key = ((unsigned long long)orderf(sm[d]) << 32) | (unsigned)(0xFFFFFFFFu - d);
        bkey = bkey > key ? bkey : key;
    }
    redu[tid] = bkey; __syncthreads();
    for (int s = 64; s > 0; s >>= 1) { if (tid < s) redu[tid] = redu[tid] > redu[tid+s] ? redu[tid] : redu[tid+s]; __syncthreads(); }
    if (tid == 0) d_greedy[bk] = (int)(0xFFFFFFFFu - (unsigned)(redu[0] & 0xFFFFFFFFu));

    for (int d = tid; d < D_; d += 128) d_lpt[bk*D_ + d] = sm[d] - logZ;

    if (t > 0) {
        float lpc = d_logp[src][bk], Gc = d_G[src][bk];
        __syncthreads();
        for (int d = tid; d < D_; d += 128) {
            float uu = fminf(fmaxf(u_t[bk*D_ + d], 1e-9f), 1.f - 1e-9f);
            float gum = -logf(-logf(uu));
            sm[d] = (sm[d] - logZ) + lpc + gum;    // g_phi
        }
        __syncthreads();
        float m2 = NEG_INF;
        for (int d = tid; d < D_; d += 128) m2 = fmaxf(m2, sm[d]);
        red[tid] = m2; __syncthreads();
        for (int s = 64; s > 0; s >>= 1) { if (tid < s) red[tid] = fmaxf(red[tid], red[tid+s]); __syncthreads(); }
        float Zm = red[0];
        for (int d = tid; d < D_; d += 128) {
            float gp = sm[d];
            float v = Gc - gp + log1pf(-expf(gp - Zm));
            float g = Gc - fmaxf(v, 0.f) - log1pf(expf(-fabsf(v)));
            d_gm[bk*D_ + d] = g;
        }
    }
}

// per image: top-8 of the 3200 candidates g2[b, k*400+d] = g[(k*64+b), d]
__global__ void topk_kernel()
{
    int b = blockIdx.x, tid = threadIdx.x;  // 128 threads
    __shared__ unsigned long long red[128];
    __shared__ unsigned long long picked[K_];
    for (int it = 0; it < K_; it++) {
        unsigned long long best = 0ull;
        for (int cidx = tid; cidx < K_*D_; cidx += 128) {
            int k = cidx / D_, d = cidx - k*D_;
            float v = d_gm[(k*B_ + b)*D_ + d];
            unsigned long long key = ((unsigned long long)orderf(v) << 32) | (unsigned)(0xFFFFFFFFu - cidx);
            bool skip = false;
            for (int j = 0; j < it; j++) if (picked[j] == key) skip = true;
            if (!skip) best = best > key ? best : key;
        }
        red[tid] = best; __syncthreads();
        for (int s = 64; s > 0; s >>= 1) { if (tid < s) red[tid] = red[tid] > red[tid+s] ? red[tid] : red[tid+s]; __syncthreads(); }
        if (tid == 0) {
            unsigned long long w = red[0];
            picked[it] = w;
            d_idxk[b*K_ + it] = (int)(0xFFFFFFFFu - (unsigned)(w & 0xFFFFFFFFu));
            d_gval[b*K_ + it] = unorderf((unsigned)(w >> 32));
        }
        __syncthreads();
    }
}

__global__ void beam_update(int t, int src)
{
    int bk = threadIdx.x;       // 512 threads, 1 block
    int dst = src ^ 1;
    int k = bk >> 6, b = bk & 63;
    int order, sample; float Gn;
    if (t == 0) { order = bk; sample = d_greedy[bk]; Gn = d_G[src][bk]; }
    else {
        int cidx = d_idxk[b*K_ + k];
        int ks = cidx / D_; sample = cidx - ks*D_;
        order = ks*B_ + b;
        Gn = d_gval[b*K_ + k];
    }
    float sel = d_lpt[order*D_ + sample];
    float lp = d_logp[src][order] + ((t == 0) ? 0.f : sel);
    d_G[dst][bk] = Gn; d_logp[dst][bk] = lp; d_order[bk] = order;
    for (int tt = 0; tt < T_; tt++) {
        d_samp[dst][bk*T_ + tt] = d_samp[src][order*T_ + tt];
        d_outs[dst][bk*T_ + tt] = d_outs[src][order*T_ + tt];
    }
    d_samp[dst][bk*T_ + t] = (float)sample;
    d_outs[dst][bk*T_ + t] = sel;
}

__global__ void gather_hc()
{
    int i = blockIdx.x * blockDim.x + threadIdx.x;
    if (i >= BK_*H_) return;
    int bk = i >> 11, col = i & 2047;
    int o = d_order[bk];
    d_h[i] = d_h2[o*H_ + col];
    d_c[i] = d_c2[o*H_ + col];
}

__global__ void entfull_kernel(const int* __restrict__ pop_t, const float* __restrict__ mask)
{
    int warp = threadIdx.x >> 5, lane = threadIdx.x & 31;
    int bk = blockIdx.x * 8 + warp;      // 64 blocks x 8 warps
    int o = d_order[bk];
    const float* lpr = d_lpt + o*D_;
    const float* mrow = mask + (size_t)pop_t[o] * D_;
    float s = 0.f;
    for (int d = lane; d < D_; d += 32) {
        float lp = lpr[d];
        if (mrow[d] == 0.f) s += lp * expf(lp);
    }
    for (int off = 16; off; off >>= 1) s += __shfl_down_sync(0xffffffffu, s, off);
    if (lane == 0) d_entfull[bk] = s;
}

__global__ void wq_kernel(int dst)
{
    int b = threadIdx.x;
    if (b >= B_) return;
    float gk = d_gval[b*K_ + (K_-1)];
    float wsum = 0.f, upd = 0.f;
    for (int k = 0; k < KM1_; k++) {
        float phi = d_logp[dst][k*B_ + b];
        float x = gk - phi;
        float gls;
        if (x >= 10.f) { float y = expf(-x); gls = -x - 0.5f*y + y*y*(1.f/24.f); }
        else gls = logf(-expm1f(-expf(-x)));
        float w = expf(phi - gls);
        d_wpq[b*KM1_ + k] = w;
        d_lgp[b*KM1_ + k] = phi;
        wsum += w;
        upd  += w * d_entfull[k*B_ + b];
    }
    d_ent[b] += upd / wsum;
}

__global__ void epilogue(float* __restrict__ out)
{
    int i = blockIdx.x * blockDim.x + threadIdx.x;
    if (i >= 11712) return;
    if (i < 5376) {
        int b = i / 84, r = i % 84, k = r / T_, tt = r % T_;
        out[i] = d_outs[0][(k*B_ + b)*T_ + tt];
    } else if (i < 10752) {
        int q = i - 5376; int b = q / 84, r = q % 84, k = r / T_, tt = r % T_;
        out[i] = d_samp[0][(k*B_ + b)*T_ + tt];
    } else if (i < 10816) out[i] = d_ent[i - 10752];
    else if (i < 11264)   out[i] = d_wpq[i - 10816];
    else                  out[i] = d_lgp[i - 11264];
}

// ---------------- launch ----------------
extern "C" void kernel_launch(void* const* d_in, const int* in_sizes, int n_in,
                              void* d_out, int out_size)
{
    const float* x_f   = (const float*)d_in[0];
    const float* x_f3  = (const float*)d_in[1];
    const float* gum_u = (const float*)d_in[2];
    const int*   pop   = (const int*)  d_in[3];
    const float* mask  = (const float*)d_in[4];
    const float* W_emb = (const float*)d_in[5];
    const float* b_emb = (const float*)d_in[6];
    const float* W_ih  = (const float*)d_in[7];
    const float* W_hh  = (const float*)d_in[8];
    const float* b_ih  = (const float*)d_in[9];
    const float* b_hh  = (const float*)d_in[10];
    const float* W_fc1 = (const float*)d_in[11];
    const float* b_fc1 = (const float*)d_in[12];
    const float* W_out = (const float*)d_in[13];
    const float* b_out = (const float*)d_in[14];

    float *pZpre, *pEmb, *pZxB, *pZ, *ph, *ph2, *phd, *plogits, *pzxbp, *plogp;
    cudaGetSymbolAddress((void**)&pZpre,   d_Zpre);
    cudaGetSymbolAddress((void**)&pEmb,    d_Emb);
    cudaGetSymbolAddress((void**)&pZxB,    d_ZxB);
    cudaGetSymbolAddress((void**)&pZ,      d_Z);
    cudaGetSymbolAddress((void**)&ph,      d_h);
    cudaGetSymbolAddress((void**)&ph2,     d_h2);
    cudaGetSymbolAddress((void**)&phd,     d_hd);
    cudaGetSymbolAddress((void**)&plogits, d_logits);
    cudaGetSymbolAddress((void**)&pzxbp,   d_zxbpart);
    cudaGetSymbolAddress((void**)&plogp,   d_logpart);

    zero_init<<<2048, 512>>>();
    emb_kernel<<<(T_*BK_*E_ + 255)/256, 256>>>(pop, W_emb, b_emb);

    // ZxB = x_f @ W_ih[:, :IN].T   [64, 8192], split-K 4x512 -> reduce
    gemm_tpl<64,128><<<dim3(G4H_/128, 1, 4), 256>>>(
        x_f, IN_, W_ih, LDIH_, nullptr, nullptr, nullptr, nullptr,
        pzxbp, G4H_, B_, G4H_, IN_, 0, 512);
    reduce_k<<<(B_*G4H_ + 255)/256, 256>>>(pzxbp, 4, B_*G4H_, G4H_, nullptr, pZxB);

    // Zpre = Emb @ W_ih[:, IN:IN+E].T + (b_ih + b_hh + ZxB[b])   [6144, 8192], K=128
    gemm_tpl<128,128><<<dim3(G4H_/128, T_*BK_/128), 256>>>(
        pEmb, E_, W_ih + IN_, LDIH_, nullptr, b_ih, b_hh, pZxB,
        pZpre, G4H_, T_*BK_, G4H_, E_, 0, 0);

    // Zpre += x_f3 @ W_ih[:, IN+E:].T      [6144, 8192], K=2048   (dominant GEMM)
    gemm_tpl<128,128><<<dim3(G4H_/128, T_*BK_/128), 256>>>(
        x_f3, IN_, W_ih + IN_ + E_, LDIH_, pZpre, nullptr, nullptr, nullptr,
        pZpre, G4H_, T_*BK_, G4H_, IN_, 0, 0);

    for (int t = 0; t < T_; t++) {
        int src = t & 1;
        // Z = h @ W_hh.T + Zpre[t]
        gemm_tpl<128,128><<<dim3(G4H_/128, BK_/128), 256>>>(
            ph, H_, W_hh, H_, pZpre + (size_t)t*BK_*G4H_, nullptr, nullptr, nullptr,
            pZ, G4H_, BK_, G4H_, H_, 0, 0);
        lstm_pw<<<(BK_*H_ + 255)/256, 256>>>();
        // hd = relu(h2 @ W_fc1.T + b_fc1)   [512, 2048]  -> 64x128 tiles, 128 CTAs
        gemm_tpl<64,128><<<dim3(H_/128, BK_/64), 256>>>(
            ph2, H_, W_fc1, H_, nullptr, b_fc1, nullptr, nullptr,
            phd, H_, BK_, H_, H_, 1, 0);
        // logits = hd @ W_out.T + b_out     [512, 400], split-K 4x512 -> reduce
        gemm_tpl<64,128><<<dim3((D_+127)/128, BK_/64, 4), 256>>>(
            phd, H_, W_out, H_, nullptr, nullptr, nullptr, nullptr,
            plogp, D_, BK_, D_, H_, 0, 512);
        reduce_k<<<(BK_*D_ + 255)/256, 256>>>(plogp, 4, BK_*D_, D_, b_out, plogits);

        softmax_kernel<<<BK_, 128>>>(pop + t*BK_, mask, gum_u + (size_t)t*BK_*D_, t, src);
        if (t > 0) topk_kernel<<<B_, 128>>>();
        beam_update<<<1, BK_>>>(t, src);
        gather_hc<<<(BK_*H_ + 255)/256, 256>>>();
        if (t > 0) {
            entfull_kernel<<<B_, 256>>>(pop + t*BK_, mask);
            wq_kernel<<<1, B_>>>(src ^ 1);
        }
    }
    epilogue<<<(11712 + 255)/256, 256>>>((float*)d_out);
}

// round 5
// speedup vs baseline: 1.9248x; 1.0015x over previous
#include <cuda_runtime.h>
#include <math.h>

#define B_    64
#define K_    8
#define T_    12
#define H_    2048
#define IN_   2048
#define D_    400
#define E_    128
#define BK_   512
#define G4H_  8192
#define LDIH_ 4224
#define KM1_  7

// ---------------- persistent device scratch (no allocation allowed) ----------------
__device__ float d_Zpre[T_*BK_*G4H_];        // 201 MB: precomputed input-side z per step
__device__ float d_Emb[T_*BK_*E_];
__device__ float d_ZxB[B_*G4H_];
__device__ float d_zxbpart[4*B_*G4H_];
__device__ float d_logpart[4*BK_*D_];
__device__ float d_Z[BK_*G4H_];
__device__ float d_h[BK_*H_];
__device__ float d_c[BK_*H_];
__device__ float d_h2[BK_*H_];
__device__ float d_c2[BK_*H_];
__device__ float d_hd[BK_*H_];
__device__ float d_logits[BK_*D_];
__device__ float d_lpt[BK_*D_];
__device__ float d_gm[BK_*D_];
__device__ float d_G[2][BK_];
__device__ float d_logp[2][BK_];
__device__ float d_samp[2][BK_*T_];
__device__ float d_outs[2][BK_*T_];
__device__ float d_ent[B_];
__device__ float d_wpq[B_*KM1_];
__device__ float d_lgp[B_*KM1_];
__device__ int   d_greedy[BK_];
__device__ int   d_order[BK_];
__device__ int   d_idxk[B_*K_];
__device__ float d_gval[B_*K_];
__device__ float d_entfull[BK_];

__device__ __forceinline__ float sigf(float x) { return 1.f / (1.f + expf(-x)); }

__device__ __forceinline__ unsigned orderf(float f) {
    unsigned u = __float_as_uint(f);
    return (u & 0x80000000u) ? ~u : (u | 0x80000000u);
}
__device__ __forceinline__ float unorderf(unsigned e) {
    unsigned b = (e & 0x80000000u) ? (e ^ 0x80000000u) : ~e;
    return __uint_as_float(b);
}

__device__ __forceinline__ unsigned long long pk2(float lo, float hi) {
    unsigned long long r;
    asm("mov.b64 %0, {%1, %2};" : "=l"(r) : "f"(lo), "f"(hi));
    return r;
}
__device__ __forceinline__ void upk2(unsigned long long v, float& lo, float& hi) {
    asm("mov.b64 {%0, %1}, %2;" : "=f"(lo), "=f"(hi) : "l"(v));
}

// =====================================================================
// Double-buffered fp32 GEMM with packed FFMA2 (fma.rn.f32x2):
//   C = act(A @ B^T [+ Cin] [+ bias] [+ bias2] [+ zxb[m&63]])
// A: [M,K] lda (K-contig), B: [N,K] ldb (K-contig), C/Cin: [M,N] ldc.
// BK = 16, 256 threads, thread tile (BM/16)x8, acc packed in pairs along M.
// If kchunk != 0: split-K along gridDim.z; partial outputs stacked in C.
// =====================================================================
template<int BM, int BN>
__global__ __launch_bounds__(256, 2)
void gemm_tpl(const float* __restrict__ A, int lda,
              const float* __restrict__ Bm, int ldb,
              const float* __restrict__ Cin,
              const float* __restrict__ bias,
              const float* __restrict__ bias2,
              const float* __restrict__ zxb,
              float* __restrict__ C, int ldc,
              int M, int N, int K, int do_relu, int kchunk)
{
    static_assert(BN == 128, "BN must be 128");
    constexpr int TM = BM / 16;          // 8 or 4
    constexpr int TN = 8;
    constexpr int LA = BM / 64;
    constexpr int LB = BN / 64;
    constexpr int BMP = BM + 4;
    constexpr int BNP = BN + 4;

    if (kchunk) {
        int kz = blockIdx.z;
        A  += (size_t)kz * kchunk;
        Bm += (size_t)kz * kchunk;
        C  += (size_t)kz * M * ldc;
        K = kchunk;
    }

    __shared__ float As[2][16][BMP];
    __shared__ float Bs[2][16][BNP];

    const int tid = threadIdx.x;
    const int bm = blockIdx.y * BM;
    const int bn = blockIdx.x * BN;
    const int tx = tid & 15;
    const int ty = tid >> 4;

    unsigned long long acc2[TM/2][TN];
#pragma unroll
    for (int i = 0; i < TM/2; i++)
#pragma unroll
        for (int j = 0; j < TN; j++) acc2[i][j] = 0ull;

    float4 pa[LA], pb[LB];

    auto fetch = [&](int k0) {
#pragma unroll
        for (int i = 0; i < LA; i++) {
            int lin = tid + 256 * i;
            int r = lin >> 2, kq = (lin & 3) << 2;
            int gr = bm + r;
            pa[i] = (gr < M) ? *reinterpret_cast<const float4*>(A + (size_t)gr * lda + k0 + kq)
                             : make_float4(0.f, 0.f, 0.f, 0.f);
        }
#pragma unroll
        for (int i = 0; i < LB; i++) {
            int lin = tid + 256 * i;
            int r = lin >> 2, kq = (lin & 3) << 2;
            int gr = bn + r;
            pb[i] = (gr < N) ? *reinterpret_cast<const float4*>(Bm + (size_t)gr * ldb + k0 + kq)
                             : make_float4(0.f, 0.f, 0.f, 0.f);
        }
    };

    auto stage = [&](int buf) {
#pragma unroll
        for (int i = 0; i < LA; i++) {
            int lin = tid + 256 * i;
            int r = lin >> 2, kq = (lin & 3) << 2;
            As[buf][kq + 0][r] = pa[i].x;
            As[buf][kq + 1][r] = pa[i].y;
            As[buf][kq + 2][r] = pa[i].z;
            As[buf][kq + 3][r] = pa[i].w;
        }
#pragma unroll
        for (int i = 0; i < LB; i++) {
            int lin = tid + 256 * i;
            int r = lin >> 2, kq = (lin & 3) << 2;
            Bs[buf][kq + 0][r] = pb[i].x;
            Bs[buf][kq + 1][r] = pb[i].y;
            Bs[buf][kq + 2][r] = pb[i].z;
            Bs[buf][kq + 3][r] = pb[i].w;
        }
    };

    auto compute = [&](int buf) {
#pragma unroll
        for (int kk = 0; kk < 16; kk++) {
            // A pairs straight from smem (broadcast across the 16 lanes of a ty-group)
            unsigned long long ap[TM/2];
#pragma unroll
            for (int i2 = 0; i2 < TM/2; i2++) {
                int off;
                if (TM == 8) off = (i2 < 2) ? (ty*4 + 2*i2) : (64 + ty*4 + 2*(i2-2));
                else         off = ty*4 + 2*i2;
                ap[i2] = *reinterpret_cast<const unsigned long long*>(&As[buf][kk][off]);
            }
            // B fragment: two conflict-free contiguous float4 reads, then splat
            float b[TN];
            {
                float4 v = *reinterpret_cast<const float4*>(&Bs[buf][kk][tx*4]);
                b[0]=v.x; b[1]=v.y; b[2]=v.z; b[3]=v.w;
                float4 w = *reinterpret_cast<const float4*>(&Bs[buf][kk][64 + tx*4]);
                b[4]=w.x; b[5]=w.y; b[6]=w.z; b[7]=w.w;
            }
            unsigned long long bs[TN];
#pragma unroll
            for (int j = 0; j < TN; j++) bs[j] = pk2(b[j], b[j]);
#pragma unroll
            for (int i2 = 0; i2 < TM/2; i2++)
#pragma unroll
                for (int j = 0; j < TN; j++)
                    asm("fma.rn.f32x2 %0, %1, %2, %0;"
                        : "+l"(acc2[i2][j]) : "l"(ap[i2]), "l"(bs[j]));
        }
    };

    fetch(0);
    stage(0);
    __syncthreads();

    int buf = 0;
    for (int k0 = 16; k0 < K; k0 += 16) {
        fetch(k0);
        compute(buf);
        stage(buf ^ 1);
        __syncthreads();
        buf ^= 1;
    }
    compute(buf);

    // epilogue
#pragma unroll
    for (int i2 = 0; i2 < TM/2; i2++) {
        int mo;
        if (TM == 8) mo = (i2 < 2) ? (ty*4 + 2*i2) : (64 + ty*4 + 2*(i2-2));
        else         mo = ty*4 + 2*i2;
#pragma unroll
        for (int j = 0; j < TN; j++) {
            int n = bn + ((j < 4) ? (tx*4 + j) : (64 + tx*4 + (j-4)));
            if (n >= N) continue;
            float lo, hi;
            upk2(acc2[i2][j], lo, hi);
#pragma unroll
            for (int r = 0; r < 2; r++) {
                int m = bm + mo + r;
                if (m >= M) continue;
                float v = (r == 0) ? lo : hi;
                if (Cin)   v += Cin[(size_t)m * ldc + n];
                if (bias)  v += bias[n];
                if (bias2) v += bias2[n];
                if (zxb)   v += zxb[(size_t)(m & 63) * ldc + n];
                if (do_relu) v = fmaxf(v, 0.f);
                C[(size_t)m * ldc + n] = v;
            }
        }
    }
}

// deterministic split-K reduction: out[i] = sum_p parts[p*total+i] (+ bias[i%ncols])
__global__ void reduce_k(const float* __restrict__ parts, int nparts, int total,
                         int ncols, const float* __restrict__ bias,
                         float* __restrict__ out)
{
    int i = blockIdx.x * blockDim.x + threadIdx.x;
    if (i >= total) return;
    float s = 0.f;
    for (int p = 0; p < nparts; p++) s += parts[(size_t)p * total + i];
    if (bias) s += bias[i % ncols];
    out[i] = s;
}

// ---------------- small kernels ----------------
__global__ void zero_init()
{
    int i = blockIdx.x * blockDim.x + threadIdx.x;
    int stride = gridDim.x * blockDim.x;
    for (int j = i; j < BK_*H_; j += stride) { d_h[j] = 0.f; d_c[j] = 0.f; }
    if (i < BK_)     { d_G[0][i] = 0.f; d_logp[0][i] = 0.f; }
    if (i < BK_*T_)  { d_samp[0][i] = 0.f; d_outs[0][i] = 0.f; }
    if (i < B_)      d_ent[i] = 0.f;
}

__global__ void emb_kernel(const int* __restrict__ pop_all,
                           const float* __restrict__ W_emb,
                           const float* __restrict__ b_emb)
{
    int i = blockIdx.x * blockDim.x + threadIdx.x;
    if (i >= T_*BK_*E_) return;
    int row = i >> 7, e = i & 127;
    int p = pop_all[row];
    float v = W_emb[e*D_ + p] + b_emb[e];
    d_Emb[i] = fmaxf(v, 0.f);
}

__global__ void lstm_pw()
{
    int i = blockIdx.x * blockDim.x + threadIdx.x;
    if (i >= BK_*H_) return;
    int bk = i >> 11, col = i & 2047;
    const float* zr = d_Z + (size_t)bk * G4H_;
    float zi = zr[col], zf = zr[H_ + col], zg = zr[2*H_ + col], zo = zr[3*H_ + col];
    float cn = sigf(zf) * d_c[i] + sigf(zi) * tanhf(zg);
    d_c2[i] = cn;
    d_h2[i] = sigf(zo) * tanhf(cn);
}

// per-row (bk): masked log_softmax, greedy argmax, and (t>0) the Gumbel-max perturbation g
__global__ void softmax_kernel(const int* __restrict__ pop_t, const float* __restrict__ mask,
                               const float* __restrict__ u_t, int t, int src)
{
    int bk = blockIdx.x, tid = threadIdx.x;   // 128 threads
    __shared__ float sm[D_];
    __shared__ float red[128];
    __shared__ unsigned long long redu[128];
    const float* lrow = d_logits + bk*D_;
    const float* mrow = mask + (size_t)pop_t[bk] * D_;
    float NEG_INF = __int_as_float(0xff800000);

    float lmax = NEG_INF;
    for (int d = tid; d < D_; d += 128) { float v = lrow[d] + mrow[d]; sm[d] = v; lmax = fmaxf(lmax, v); }
    red[tid] = lmax; __syncthreads();
    for (int s = 64; s > 0; s >>= 1) { if (tid < s) red[tid] = fmaxf(red[tid], red[tid+s]); __syncthreads(); }
    float M = red[0]; __syncthreads();

    float ssum = 0.f;
    for (int d = tid; d < D_; d += 128) ssum += expf(sm[d] - M);
    red[tid] = ssum; __syncthreads();
    for (int s = 64; s > 0; s >>= 1) { if (tid < s) red[tid] += red[tid+s]; __syncthreads(); }
    float logZ = M + logf(red[0]);

    // greedy argmax with jax first-index tie-break
    unsigned long long bkey = 0ull;
    for (int d = tid; d < D_; d += 128) {
        unsigned long long key = ((unsigned long long)orderf(sm[d]) << 32) | (unsigned)(0xFFFFFFFFu - d);
        bkey = bkey > key ? bkey : key;
    }
    redu[tid] = bkey; __syncthreads();
    for (int s = 64; s > 0; s >>= 1) { if (tid < s) redu[tid] = redu[tid] > redu[tid+s] ? redu[tid] : redu[tid+s]; __syncthreads(); }
    if (tid == 0) d_greedy[bk] = (int)(0xFFFFFFFFu - (unsigned)(redu[0] & 0xFFFFFFFFu));

    for (int d = tid; d < D_; d += 128) d_lpt[bk*D_ + d] = sm[d] - logZ;

    if (t > 0) {
        float lpc = d_logp[src][bk], Gc = d_G[src][bk];
        __syncthreads();
        for (int d = tid; d < D_; d += 128) {
            float uu = fminf(fmaxf(u_t[bk*D_ + d], 1e-9f), 1.f - 1e-9f);
            float gum = -logf(-logf(uu));
            sm[d] = (sm[d] - logZ) + lpc + gum;    // g_phi
        }
        __syncthreads();
        float m2 = NEG_INF;
        for (int d = tid; d < D_; d += 128) m2 = fmaxf(m2, sm[d]);
        red[tid] = m2; __syncthreads();
        for (int s = 64; s > 0; s >>= 1) { if (tid < s) red[tid] = fmaxf(red[tid], red[tid+s]); __syncthreads(); }
        float Zm = red[0];
        for (int d = tid; d < D_; d += 128) {
            float gp = sm[d];
            float v = Gc - gp + log1pf(-expf(gp - Zm));
            float g = Gc - fmaxf(v, 0.f) - log1pf(expf(-fabsf(v)));
            d_gm[bk*D_ + d] = g;
        }
    }
}

// per image: top-8 of the 3200 candidates g2[b, k*400+d] = g[(k*64+b), d]
__global__ void topk_kernel()
{
    int b = blockIdx.x, tid = threadIdx.x;  // 128 threads
    __shared__ unsigned long long red[128];
    __shared__ unsigned long long picked[K_];
    for (int it = 0; it < K_; it++) {
        unsigned long long best = 0ull;
        for (int cidx = tid; cidx < K_*D_; cidx += 128) {
            int k = cidx / D_, d = cidx - k*D_;
            float v = d_gm[(k*B_ + b)*D_ + d];
            unsigned long long key = ((unsigned long long)orderf(v) << 32) | (unsigned)(0xFFFFFFFFu - cidx);
            bool skip = false;
            for (int j = 0; j < it; j++) if (picked[j] == key) skip = true;
            if (!skip) best = best > key ? best : key;
        }
        red[tid] = best; __syncthreads();
        for (int s = 64; s > 0; s >>= 1) { if (tid < s) red[tid] = red[tid] > red[tid+s] ? red[tid] : red[tid+s]; __syncthreads(); }
        if (tid == 0) {
            unsigned long long w = red[0];
            picked[it] = w;
            d_idxk[b*K_ + it] = (int)(0xFFFFFFFFu - (unsigned)(w & 0xFFFFFFFFu));
            d_gval[b*K_ + it] = unorderf((unsigned)(w >> 32));
        }
        __syncthreads();
    }
}

__global__ void beam_update(int t, int src)
{
    int bk = threadIdx.x;       // 512 threads, 1 block
    int dst = src ^ 1;
    int k = bk >> 6, b = bk & 63;
    int order, sample; float Gn;
    if (t == 0) { order = bk; sample = d_greedy[bk]; Gn = d_G[src][bk]; }
    else {
        int cidx = d_idxk[b*K_ + k];
        int ks = cidx / D_; sample = cidx - ks*D_;
        order = ks*B_ + b;
        Gn = d_gval[b*K_ + k];
    }
    float sel = d_lpt[order*D_ + sample];
    float lp = d_logp[src][order] + ((t == 0) ? 0.f : sel);
    d_G[dst][bk] = Gn; d_logp[dst][bk] = lp; d_order[bk] = order;
    for (int tt = 0; tt < T_; tt++) {
        d_samp[dst][bk*T_ + tt] = d_samp[src][order*T_ + tt];
        d_outs[dst][bk*T_ + tt] = d_outs[src][order*T_ + tt];
    }
    d_samp[dst][bk*T_ + t] = (float)sample;
    d_outs[dst][bk*T_ + t] = sel;
}

__global__ void gather_hc()
{
    int i = blockIdx.x * blockDim.x + threadIdx.x;
    if (i >= BK_*H_) return;
    int bk = i >> 11, col = i & 2047;
    int o = d_order[bk];
    d_h[i] = d_h2[o*H_ + col];
    d_c[i] = d_c2[o*H_ + col];
}

__global__ void entfull_kernel(const int* __restrict__ pop_t, const float* __restrict__ mask)
{
    int warp = threadIdx.x >> 5, lane = threadIdx.x & 31;
    int bk = blockIdx.x * 8 + warp;      // 64 blocks x 8 warps
    int o = d_order[bk];
    const float* lpr = d_lpt + o*D_;
    const float* mrow = mask + (size_t)pop_t[o] * D_;
    float s = 0.f;
    for (int d = lane; d < D_; d += 32) {
        float lp = lpr[d];
        if (mrow[d] == 0.f) s += lp * expf(lp);
    }
    for (int off = 16; off; off >>= 1) s += __shfl_down_sync(0xffffffffu, s, off);
    if (lane == 0) d_entfull[bk] = s;
}

__global__ void wq_kernel(int dst)
{
    int b = threadIdx.x;
    if (b >= B_) return;
    float gk = d_gval[b*K_ + (K_-1)];
    float wsum = 0.f, upd = 0.f;
    for (int k = 0; k < KM1_; k++) {
        float phi = d_logp[dst][k*B_ + b];
        float x = gk - phi;
        float gls;
        if (x >= 10.f) { float y = expf(-x); gls = -x - 0.5f*y + y*y*(1.f/24.f); }
        else gls = logf(-expm1f(-expf(-x)));
        float w = expf(phi - gls);
        d_wpq[b*KM1_ + k] = w;
        d_lgp[b*KM1_ + k] = phi;
        wsum += w;
        upd  += w * d_entfull[k*B_ + b];
    }
    d_ent[b] += upd / wsum;
}

__global__ void epilogue(float* __restrict__ out)
{
    int i = blockIdx.x * blockDim.x + threadIdx.x;
    if (i >= 11712) return;
    if (i < 5376) {
        int b = i / 84, r = i % 84, k = r / T_, tt = r % T_;
        out[i] = d_outs[0][(k*B_ + b)*T_ + tt];
    } else if (i < 10752) {
        int q = i - 5376; int b = q / 84, r = q % 84, k = r / T_, tt = r % T_;
        out[i] = d_samp[0][(k*B_ + b)*T_ + tt];
    } else if (i < 10816) out[i] = d_ent[i - 10752];
    else if (i < 11264)   out[i] = d_wpq[i - 10816];
    else                  out[i] = d_lgp[i - 11264];
}

// ---------------- launch ----------------
extern "C" void kernel_launch(void* const* d_in, const int* in_sizes, int n_in,
                              void* d_out, int out_size)
{
    const float* x_f   = (const float*)d_in[0];
    const float* x_f3  = (const float*)d_in[1];
    const float* gum_u = (const float*)d_in[2];
    const int*   pop   = (const int*)  d_in[3];
    const float* mask  = (const float*)d_in[4];
    const float* W_emb = (const float*)d_in[5];
    const float* b_emb = (const float*)d_in[6];
    const float* W_ih  = (const float*)d_in[7];
    const float* W_hh  = (const float*)d_in[8];
    const float* b_ih  = (const float*)d_in[9];
    const float* b_hh  = (const float*)d_in[10];
    const float* W_fc1 = (const float*)d_in[11];
    const float* b_fc1 = (const float*)d_in[12];
    const float* W_out = (const float*)d_in[13];
    const float* b_out = (const float*)d_in[14];

    float *pZpre, *pEmb, *pZxB, *pZ, *ph, *ph2, *phd, *plogits, *pzxbp, *plogp;
    cudaGetSymbolAddress((void**)&pZpre,   d_Zpre);
    cudaGetSymbolAddress((void**)&pEmb,    d_Emb);
    cudaGetSymbolAddress((void**)&pZxB,    d_ZxB);
    cudaGetSymbolAddress((void**)&pZ,      d_Z);
    cudaGetSymbolAddress((void**)&ph,      d_h);
    cudaGetSymbolAddress((void**)&ph2,     d_h2);
    cudaGetSymbolAddress((void**)&phd,     d_hd);
    cudaGetSymbolAddress((void**)&plogits, d_logits);
    cudaGetSymbolAddress((void**)&pzxbp,   d_zxbpart);
    cudaGetSymbolAddress((void**)&plogp,   d_logpart);

    zero_init<<<2048, 512>>>();
    emb_kernel<<<(T_*BK_*E_ + 255)/256, 256>>>(pop, W_emb, b_emb);

    // ZxB = x_f @ W_ih[:, :IN].T   [64, 8192], split-K 4x512 -> reduce
    gemm_tpl<64,128><<<dim3(G4H_/128, 1, 4), 256>>>(
        x_f, IN_, W_ih, LDIH_, nullptr, nullptr, nullptr, nullptr,
        pzxbp, G4H_, B_, G4H_, IN_, 0, 512);
    reduce_k<<<(B_*G4H_ + 255)/256, 256>>>(pzxbp, 4, B_*G4H_, G4H_, nullptr, pZxB);

    // Zpre = Emb @ W_ih[:, IN:IN+E].T + (b_ih + b_hh + ZxB[b])   [6144, 8192], K=128
    gemm_tpl<128,128><<<dim3(G4H_/128, T_*BK_/128), 256>>>(
        pEmb, E_, W_ih + IN_, LDIH_, nullptr, b_ih, b_hh, pZxB,
        pZpre, G4H_, T_*BK_, G4H_, E_, 0, 0);

    // Zpre += x_f3 @ W_ih[:, IN+E:].T      [6144, 8192], K=2048   (dominant GEMM)
    gemm_tpl<128,128><<<dim3(G4H_/128, T_*BK_/128), 256>>>(
        x_f3, IN_, W_ih + IN_ + E_, LDIH_, pZpre, nullptr, nullptr, nullptr,
        pZpre, G4H_, T_*BK_, G4H_, IN_, 0, 0);

    for (int t = 0; t < T_; t++) {
        int src = t & 1;
        // Z = h @ W_hh.T + Zpre[t]
        gemm_tpl<128,128><<<dim3(G4H_/128, BK_/128), 256>>>(
            ph, H_, W_hh, H_, pZpre + (size_t)t*BK_*G4H_, nullptr, nullptr, nullptr,
            pZ, G4H_, BK_, G4H_, H_, 0, 0);
        lstm_pw<<<(BK_*H_ + 255)/256, 256>>>();
        // hd = relu(h2 @ W_fc1.T + b_fc1)   [512, 2048]  -> 64x128 tiles, 128 CTAs
        gemm_tpl<64,128><<<dim3(H_/128, BK_/64), 256>>>(
            ph2, H_, W_fc1, H_, nullptr, b_fc1, nullptr, nullptr,
            phd, H_, BK_, H_, H_, 1, 0);
        // logits = hd @ W_out.T + b_out     [512, 400], split-K 4x512 -> reduce
        gemm_tpl<64,128><<<dim3((D_+127)/128, BK_/64, 4), 256>>>(
            phd, H_, W_out, H_, nullptr, nullptr, nullptr, nullptr,
            plogp, D_, BK_, D_, H_, 0, 512);
        reduce_k<<<(BK_*D_ + 255)/256, 256>>>(plogp, 4, BK_*D_, D_, b_out, plogits);

        softmax_kernel<<<BK_, 128>>>(pop + t*BK_, mask, gum_u + (size_t)t*BK_*D_, t, src);
        if (t > 0) topk_kernel<<<B_, 128>>>();
        beam_update<<<1, BK_>>>(t, src);
        gather_hc<<<(BK_*H_ + 255)/256, 256>>>();
        if (t > 0) {
            entfull_kernel<<<B_, 256>>>(pop + t*BK_, mask);
            wq_kernel<<<1, B_>>>(src ^ 1);
        }
    }
    epilogue<<<(11712 + 255)/256, 256>>>((float*)d_out);
}